// round 2
// baseline (speedup 1.0000x reference)
#include <cuda_runtime.h>

// Problem constants
#define NN 50000
#define EE 1600000
#define ET (EE + NN)
#define DHD 128
#define PERM_SZ (NN + 3 * 128)

// ---------------- device scratch (no allocations allowed) ----------------
__device__ float g_y[(size_t)NN * DHD];     // gated per-node message Y
__device__ float g_bufA[(size_t)NN * DHD];  // conv accumulator A
__device__ float g_bufB[(size_t)NN * DHD];  // conv accumulator B
__device__ float g_z[(size_t)NN * DHD];     // z gate
__device__ float g_rh[(size_t)NN * DHD];    // r * h_prev
__device__ float g_WS[6 * 3 * DHD * DHD];   // per-conv per-role W@S
__device__ int g_deg[NN];
__device__ int g_off[NN + 1];
__device__ int g_pos[NN];
__device__ int g_csr[ET];
__device__ int g_roleCnt[3];
__device__ int g_rolePadOff[4];
__device__ int g_rolePos[3];
__device__ int g_perm[PERM_SZ];

typedef unsigned long long u64;

__device__ __forceinline__ u64 pack2(float x) {
    u64 r;
    asm("mov.b64 %0,{%1,%1};" : "=l"(r) : "f"(x));
    return r;
}
__device__ __forceinline__ void unpack2(u64 v, float& a, float& b) {
    asm("mov.b64 {%0,%1},%2;" : "=f"(a), "=f"(b) : "l"(v));
}
__device__ __forceinline__ void fma2(u64& d, u64 a, u64 b) {
    asm("fma.rn.f32x2 %0,%1,%2,%0;" : "+l"(d) : "l"(a), "l"(b));
}

// ---------------- preprocessing ----------------
__global__ void init_kernel() {
    int i = blockIdx.x * blockDim.x + threadIdx.x;
    if (i < NN) g_deg[i] = 0;
    if (i < 3) g_roleCnt[i] = 0;
    if (i < PERM_SZ) g_perm[i] = -1;
}

__global__ void count_kernel(const int* __restrict__ ei, const int* __restrict__ role) {
    int e = blockIdx.x * blockDim.x + threadIdx.x;
    if (e < ET) {
        int c = (e < EE) ? ei[EE + e] : (e - EE);
        atomicAdd(&g_deg[c], 1);
    }
    if (e < NN) atomicAdd(&g_roleCnt[role[e]], 1);
}

__global__ void scan_kernel() {
    __shared__ int sh[1024];
    int t = threadIdx.x;
    int total = 0;
    for (int base = 0; base < NN; base += 1024) {
        int v = (base + t < NN) ? g_deg[base + t] : 0;
        sh[t] = v;
        __syncthreads();
        for (int off = 1; off < 1024; off <<= 1) {
            int x = 0;
            if (t >= off) x = sh[t - off];
            __syncthreads();
            sh[t] += x;
            __syncthreads();
        }
        int excl = sh[t] - v;
        if (base + t < NN) {
            g_off[base + t] = total + excl;
            g_pos[base + t] = total + excl;
        }
        total += sh[1023];
        __syncthreads();
    }
    if (t == 0) {
        g_off[NN] = total;
        int o = 0;
        for (int r2 = 0; r2 < 3; r2++) {
            g_rolePadOff[r2] = o;
            g_rolePos[r2] = o;
            o += ((g_roleCnt[r2] + 127) >> 7) << 7;  // pad each role segment to 128
        }
        g_rolePadOff[3] = o;
    }
}

__global__ void fill_kernel(const int* __restrict__ ei, const int* __restrict__ role) {
    int e = blockIdx.x * blockDim.x + threadIdx.x;
    if (e < ET) {
        int r, c;
        if (e < EE) { r = ei[e]; c = ei[EE + e]; }
        else { r = e - EE; c = e - EE; }
        int p = atomicAdd(&g_pos[c], 1);
        g_csr[p] = r;
    }
    if (e < NN) {
        int q = atomicAdd(&g_rolePos[role[e]], 1);
        g_perm[q] = e;
    }
}

// ---------------- WS[conv][r] = W @ S[r] (tiny, 72 blocks total) ----------------
__global__ void __launch_bounds__(256) ws_all_kernel(
    const float* W0, const float* S0, const float* W1, const float* S1,
    const float* W2, const float* S2, const float* W3, const float* S3,
    const float* W4, const float* S4, const float* W5, const float* S5) {
    int conv = blockIdx.z, r = blockIdx.y, ct = blockIdx.x;
    const float* W;
    const float* S;
    switch (conv) {
        case 0: W = W0; S = S0; break;
        case 1: W = W1; S = S1; break;
        case 2: W = W2; S = S2; break;
        case 3: W = W3; S = S3; break;
        case 4: W = W4; S = S4; break;
        default: W = W5; S = S5; break;
    }
    const float* B = S + ((size_t)r << 14) + ct * 32;
    float* C = g_WS + (((size_t)conv * 3 + r) << 14) + ct * 32;

    __shared__ float As[DHD][33];
    __shared__ float Bs[32][33];
    int tid = threadIdx.x;
    int tr = tid >> 4, tc = tid & 15;
    float acc[8][2] = {};
    for (int kc = 0; kc < DHD; kc += 32) {
#pragma unroll
        for (int t = 0; t < 4; t++) {
            int idx = tid + t * 256;
            int row = idx >> 3;
            int kq = (idx & 7) << 2;
            float4 v = *(const float4*)&W[(size_t)row * DHD + kc + kq];
            As[row][kq] = v.x; As[row][kq + 1] = v.y; As[row][kq + 2] = v.z; As[row][kq + 3] = v.w;
        }
#pragma unroll
        for (int t = 0; t < 4; t++) {
            int idx = tid + t * 256;
            int kk = idx >> 5;
            int j = idx & 31;
            Bs[kk][j] = B[(size_t)(kc + kk) * DHD + j];
        }
        __syncthreads();
#pragma unroll 8
        for (int kk = 0; kk < 32; kk++) {
            float b0 = Bs[kk][tc * 2], b1 = Bs[kk][tc * 2 + 1];
#pragma unroll
            for (int i = 0; i < 8; i++) {
                float a = As[tr * 8 + i][kk];
                acc[i][0] += a * b0;
                acc[i][1] += a * b1;
            }
        }
        __syncthreads();
    }
#pragma unroll
    for (int i = 0; i < 8; i++) {
        C[(size_t)(tr * 8 + i) * DHD + tc * 2] = acc[i][0];
        C[(size_t)(tr * 8 + i) * DHD + tc * 2 + 1] = acc[i][1];
    }
}

// ---------------- GEMM1: Y = gate(X @ W) + b (fused epilogue) ----------------
// Block: 128 rows x 128 cols, 256 threads, f32x2 packed FMA micro-kernel.
__global__ void __launch_bounds__(256, 2) gemm_y_kernel(
    const float* __restrict__ X, const float* __restrict__ W,
    const float* __restrict__ Wg, const float* __restrict__ bg,
    const float* __restrict__ bvec, const int* __restrict__ role) {
    __shared__ float As[DHD][33];
    __shared__ __align__(16) float Bs[32][DHD];
    __shared__ float sg[3][DHD];
    __shared__ float bb[3][DHD];
    __shared__ int role_s[DHD];

    int tid = threadIdx.x;
    int r0 = blockIdx.x * DHD;
    const float* Xp = X ? X : g_rh;

    // 384 gate/bias entries loaded by 256 threads: strided loop (bug fix R1).
    for (int t = tid; t < 3 * DHD; t += 256) {
        int r = t >> 7, c = t & 127;
        float wv = Wg[r * DHD + c] + bg[r * DHD + c];
        sg[r][c] = 1.0f / (1.0f + __expf(-wv));
        bb[r][c] = bvec ? bvec[r * DHD + c] : 0.0f;
    }
    if (tid < DHD) {
        int gr = r0 + tid;
        role_s[tid] = (gr < NN) ? role[gr] : 0;
    }

    int tr = tid >> 4, tc = tid & 15;
    u64 acc[8][4];
#pragma unroll
    for (int i = 0; i < 8; i++)
#pragma unroll
        for (int j = 0; j < 4; j++) acc[i][j] = 0ull;

    for (int kc = 0; kc < DHD; kc += 32) {
#pragma unroll
        for (int t = 0; t < 4; t++) {
            int idx = tid + t * 256;
            int row = idx >> 3;
            int kq = (idx & 7) << 2;
            float4 v = make_float4(0.f, 0.f, 0.f, 0.f);
            int gr = r0 + row;
            if (gr < NN) v = *(const float4*)(Xp + (size_t)gr * DHD + kc + kq);
            As[row][kq] = v.x; As[row][kq + 1] = v.y; As[row][kq + 2] = v.z; As[row][kq + 3] = v.w;
        }
#pragma unroll
        for (int t = 0; t < 4; t++) {
            int idx = tid + t * 256;
            int kk = idx >> 5;
            int cq = (idx & 31) << 2;
            *(float4*)&Bs[kk][cq] = *(const float4*)(W + (size_t)(kc + kk) * DHD + cq);
        }
        __syncthreads();
#pragma unroll 8
        for (int kk = 0; kk < 32; kk++) {
            const u64* bp = (const u64*)(&Bs[kk][0]);
            u64 b2_0 = bp[tc], b2_1 = bp[tc + 16], b2_2 = bp[tc + 32], b2_3 = bp[tc + 48];
#pragma unroll
            for (int i = 0; i < 8; i++) {
                u64 a2 = pack2(As[tr * 8 + i][kk]);
                fma2(acc[i][0], a2, b2_0);
                fma2(acc[i][1], a2, b2_1);
                fma2(acc[i][2], a2, b2_2);
                fma2(acc[i][3], a2, b2_3);
            }
        }
        __syncthreads();
    }

#pragma unroll
    for (int i = 0; i < 8; i++) {
        int lr = tr * 8 + i;
        int rr = r0 + lr;
        if (rr >= NN) continue;
        int rl = role_s[lr];
#pragma unroll
        for (int jp = 0; jp < 4; jp++) {
            int c0 = 2 * tc + 32 * jp;
            float v0, v1;
            unpack2(acc[i][jp], v0, v1);
            float y0 = v0 * sg[rl][c0] + bb[rl][c0];
            float y1 = v1 * sg[rl][c0 + 1] + bb[rl][c0 + 1];
            *(float2*)&g_y[(size_t)rr * DHD + c0] = make_float2(y0, y1);
        }
    }
}

// ---------------- SpMM: C[i] = mean of Y[src] over incoming edges ----------------
__global__ void __launch_bounds__(256) spmm_kernel(int sel) {
    float* C = sel ? g_bufB : g_bufA;
    int w = (blockIdx.x * blockDim.x + threadIdx.x) >> 5;
    int lane = threadIdx.x & 31;
    if (w >= NN) return;
    int s = g_off[w], e = g_off[w + 1];
    float4 a0 = make_float4(0.f, 0.f, 0.f, 0.f);
    float4 a1 = make_float4(0.f, 0.f, 0.f, 0.f);
    int p = s;
    for (; p + 2 <= e; p += 2) {
        int s0 = g_csr[p], s1 = g_csr[p + 1];
        float4 v0 = *(const float4*)(g_y + (size_t)s0 * DHD + (lane << 2));
        float4 v1 = *(const float4*)(g_y + (size_t)s1 * DHD + (lane << 2));
        a0.x += v0.x; a0.y += v0.y; a0.z += v0.z; a0.w += v0.w;
        a1.x += v1.x; a1.y += v1.y; a1.z += v1.z; a1.w += v1.w;
    }
    if (p < e) {
        int s0 = g_csr[p];
        float4 v0 = *(const float4*)(g_y + (size_t)s0 * DHD + (lane << 2));
        a0.x += v0.x; a0.y += v0.y; a0.z += v0.z; a0.w += v0.w;
    }
    float inv = 1.0f / (float)(e - s);
    float4 r;
    r.x = (a0.x + a1.x) * inv;
    r.y = (a0.y + a1.y) * inv;
    r.z = (a0.z + a1.z) * inv;
    r.w = (a0.w + a1.w) * inv;
    *(float4*)(C + (size_t)w * DHD + (lane << 2)) = r;
}

// ---------------- role-grouped self GEMM: C[node] += X[node] @ WS[conv][role] ----
__global__ void __launch_bounds__(256, 2) gemm_self_kernel(
    const float* __restrict__ X, int convIdx, int sel) {
    float* C = sel ? g_bufB : g_bufA;
    const float* Xp = X ? X : g_rh;
    __shared__ float As[DHD][33];
    __shared__ __align__(16) float Bs[32][DHD];
    __shared__ int nodes[DHD];
    __shared__ int padOff_s[4];

    int tid = threadIdx.x;
    int rowBase = blockIdx.x * DHD;
    if (tid < 4) padOff_s[tid] = g_rolePadOff[tid];
    if (tid < DHD) nodes[tid] = (rowBase + tid < PERM_SZ) ? g_perm[rowBase + tid] : -1;
    __syncthreads();
    if (rowBase >= padOff_s[3]) return;
    int r = 0;
    if (rowBase >= padOff_s[1]) r = 1;
    if (rowBase >= padOff_s[2]) r = 2;
    const float* Wm = g_WS + (((size_t)convIdx * 3 + r) << 14);

    int tr = tid >> 4, tc = tid & 15;
    u64 acc[8][4];
#pragma unroll
    for (int i = 0; i < 8; i++)
#pragma unroll
        for (int j = 0; j < 4; j++) acc[i][j] = 0ull;

    for (int kc = 0; kc < DHD; kc += 32) {
#pragma unroll
        for (int t = 0; t < 4; t++) {
            int idx = tid + t * 256;
            int row = idx >> 3;
            int kq = (idx & 7) << 2;
            float4 v = make_float4(0.f, 0.f, 0.f, 0.f);
            int gr = nodes[row];
            if (gr >= 0) v = *(const float4*)(Xp + (size_t)gr * DHD + kc + kq);
            As[row][kq] = v.x; As[row][kq + 1] = v.y; As[row][kq + 2] = v.z; As[row][kq + 3] = v.w;
        }
#pragma unroll
        for (int t = 0; t < 4; t++) {
            int idx = tid + t * 256;
            int kk = idx >> 5;
            int cq = (idx & 31) << 2;
            *(float4*)&Bs[kk][cq] = *(const float4*)(Wm + (size_t)(kc + kk) * DHD + cq);
        }
        __syncthreads();
#pragma unroll 8
        for (int kk = 0; kk < 32; kk++) {
            const u64* bp = (const u64*)(&Bs[kk][0]);
            u64 b2_0 = bp[tc], b2_1 = bp[tc + 16], b2_2 = bp[tc + 32], b2_3 = bp[tc + 48];
#pragma unroll
            for (int i = 0; i < 8; i++) {
                u64 a2 = pack2(As[tr * 8 + i][kk]);
                fma2(acc[i][0], a2, b2_0);
                fma2(acc[i][1], a2, b2_1);
                fma2(acc[i][2], a2, b2_2);
                fma2(acc[i][3], a2, b2_3);
            }
        }
        __syncthreads();
    }

#pragma unroll
    for (int i = 0; i < 8; i++) {
        int node = nodes[tr * 8 + i];
        if (node < 0) continue;
#pragma unroll
        for (int jp = 0; jp < 4; jp++) {
            int c0 = 2 * tc + 32 * jp;
            float v0, v1;
            unpack2(acc[i][jp], v0, v1);
            float2 old = *(float2*)&C[(size_t)node * DHD + c0];
            old.x += v0;
            old.y += v1;
            *(float2*)&C[(size_t)node * DHD + c0] = old;
        }
    }
}

// ---------------- elementwise combines ----------------
__device__ __forceinline__ float sigm(float x) { return 1.0f / (1.0f + __expf(-x)); }

__global__ void combine_zr_kernel(const float* __restrict__ h, int mode) {
    size_t i = (size_t)blockIdx.x * blockDim.x + threadIdx.x;
    if (i >= (size_t)NN * 32) return;
    float4 a = ((const float4*)g_bufA)[i];
    float4 b = ((const float4*)g_bufB)[i];
    float4 o;
    o.x = sigm(fmaxf(a.x, 0.f) + fmaxf(b.x, 0.f));
    o.y = sigm(fmaxf(a.y, 0.f) + fmaxf(b.y, 0.f));
    o.z = sigm(fmaxf(a.z, 0.f) + fmaxf(b.z, 0.f));
    o.w = sigm(fmaxf(a.w, 0.f) + fmaxf(b.w, 0.f));
    if (mode) {
        float4 hv = ((const float4*)h)[i];
        o.x *= hv.x; o.y *= hv.y; o.z *= hv.z; o.w *= hv.w;
        ((float4*)g_rh)[i] = o;
    } else {
        ((float4*)g_z)[i] = o;
    }
}

__global__ void combine_h_kernel(const float* __restrict__ h, float* __restrict__ out) {
    size_t i = (size_t)blockIdx.x * blockDim.x + threadIdx.x;
    if (i >= (size_t)NN * 32) return;
    float4 a = ((const float4*)g_bufA)[i];
    float4 b = ((const float4*)g_bufB)[i];
    float4 zv = ((const float4*)g_z)[i];
    float4 hv = ((const float4*)h)[i];
    float4 o;
    float ht;
    ht = tanhf(fmaxf(a.x, 0.f) + fmaxf(b.x, 0.f));
    o.x = zv.x * hv.x + (1.0f - zv.x) * ht;
    ht = tanhf(fmaxf(a.y, 0.f) + fmaxf(b.y, 0.f));
    o.y = zv.y * hv.y + (1.0f - zv.y) * ht;
    ht = tanhf(fmaxf(a.z, 0.f) + fmaxf(b.z, 0.f));
    o.z = zv.z * hv.z + (1.0f - zv.z) * ht;
    ht = tanhf(fmaxf(a.w, 0.f) + fmaxf(b.w, 0.f));
    o.w = zv.w * hv.w + (1.0f - zv.w) * ht;
    ((float4*)out)[i] = o;
}

// ---------------- host launch ----------------
struct CW {
    const float *W, *Wg, *bg, *S, *b;
};

static void run_conv(const float* X, const CW& w, int convIdx, int sel, const int* role) {
    gemm_y_kernel<<<(NN + 127) / 128, 256>>>(X, w.W, w.Wg, w.bg, w.b, role);
    spmm_kernel<<<(NN * 32 + 255) / 256, 256>>>(sel);
    gemm_self_kernel<<<396, 256>>>(X, convIdx, sel);
}

extern "C" void kernel_launch(void* const* d_in, const int* in_sizes, int n_in,
                              void* d_out, int out_size) {
    // Auto-detect input ordering: dict order (x, h_prev, edge_index, node_role)
    // vs reference-signature order (x, edge_index, h_prev, node_role).
    int iEdge = 2, iH = 1;
    if (in_sizes[1] == 2 * EE) { iEdge = 1; iH = 2; }
    const float* x = (const float*)d_in[0];
    const float* h_prev = (const float*)d_in[iH];
    const int* ei = (const int*)d_in[iEdge];
    const int* role = (const int*)d_in[3];

    const float* P[27];
    for (int i = 0; i < 27 && (4 + i) < n_in; i++) P[i] = (const float*)d_in[4 + i];
    // Per-conv weight layout (both orderings agree): W, Wg, bg, S, [b]
    CW xz{P[0], P[1], P[2], P[3], P[4]};
    CW hz{P[5], P[6], P[7], P[8], nullptr};
    CW xr{P[9], P[10], P[11], P[12], P[13]};
    CW hr{P[14], P[15], P[16], P[17], nullptr};
    CW xh{P[18], P[19], P[20], P[21], P[22]};
    CW hh{P[23], P[24], P[25], P[26], nullptr};
    float* out = (float*)d_out;

    // Preprocess: CSR by destination + role-grouped node permutation
    init_kernel<<<(PERM_SZ + 255) / 256, 256>>>();
    count_kernel<<<(ET + 255) / 256, 256>>>(ei, role);
    scan_kernel<<<1, 1024>>>();
    fill_kernel<<<(ET + 255) / 256, 256>>>(ei, role);
    ws_all_kernel<<<dim3(4, 3, 6), 256>>>(xz.W, xz.S, hz.W, hz.S, xr.W, xr.S,
                                          hr.W, hr.S, xh.W, xh.S, hh.W, hh.S);

    // z gate
    run_conv(x, xz, 0, 0, role);
    run_conv(h_prev, hz, 1, 1, role);
    combine_zr_kernel<<<(NN * 32 + 255) / 256, 256>>>(h_prev, 0);
    // r gate -> r * h_prev
    run_conv(x, xr, 2, 0, role);
    run_conv(h_prev, hr, 3, 1, role);
    combine_zr_kernel<<<(NN * 32 + 255) / 256, 256>>>(h_prev, 1);
    // h_tilde + final GRU mix (hh conv input = g_rh, signalled via X=nullptr)
    run_conv(x, xh, 4, 0, role);
    run_conv(nullptr, hh, 5, 1, role);
    combine_h_kernel<<<(NN * 32 + 255) / 256, 256>>>(h_prev, out);
}